// round 7
// baseline (speedup 1.0000x reference)
#include <cuda_runtime.h>
#include <math.h>

#define Bz 2
#define Sq 2048
#define Dm 1024
#define Hn 16
#define DH 64
#define NREL 129
#define BHN (Bz*Hn)

typedef unsigned long long ull;

__device__ float g_Q[BHN * Sq * DH];
__device__ float g_K[BHN * Sq * DH];
__device__ float g_V[BHN * Sq * DH];

__device__ __forceinline__ ull pack2(float lo, float hi) {
    ull r; asm("mov.b64 %0, {%1, %2};" : "=l"(r) : "f"(lo), "f"(hi)); return r;
}
__device__ __forceinline__ float2 unpack2(ull v) {
    float2 r; asm("mov.b64 {%0, %1}, %2;" : "=f"(r.x), "=f"(r.y) : "l"(v)); return r;
}
__device__ __forceinline__ void fma2(ull& a, ull x, ull y) {
    asm("fma.rn.f32x2 %0, %1, %2, %0;" : "+l"(a) : "l"(x), "l"(y));
}
__device__ __forceinline__ ull mul2(ull x, ull y) {
    ull r; asm("mul.rn.f32x2 %0, %1, %2;" : "=l"(r) : "l"(x), "l"(y)); return r;
}
__device__ __forceinline__ void cp16(float* dst, const float* src) {
    unsigned a = (unsigned)__cvta_generic_to_shared(dst);
    asm volatile("cp.async.cg.shared.global [%0], [%1], 16;" :: "r"(a), "l"(src) : "memory");
}

// ---------------------------------------------------------------------------
// Kernel 1: QKV projection. 128x128 tile, k-step 16, 8x8 micro, FFMA2.
// (unchanged from round 5 — known good)
// ---------------------------------------------------------------------------
__global__ __launch_bounds__(256, 2)
void qkv_proj_kernel(const float* __restrict__ Xq, const float* __restrict__ Xk,
                     const float* __restrict__ Xv,
                     const float* __restrict__ Wq, const float* __restrict__ Wk,
                     const float* __restrict__ Wv,
                     const float* __restrict__ bq, const float* __restrict__ bk,
                     const float* __restrict__ bv)
{
    const float* X; const float* W; const float* bias; float* outp;
    if (blockIdx.z == 0)      { X = Xq; W = Wq; bias = bq; outp = g_Q; }
    else if (blockIdx.z == 1) { X = Xk; W = Wk; bias = bk; outp = g_K; }
    else                      { X = Xv; W = Wv; bias = bv; outp = g_V; }

    __shared__ __align__(16) float Xs[16][132];
    __shared__ __align__(16) float Ws[16][132];

    const int tid = threadIdx.x;
    const int tx = tid & 15, ty = tid >> 4;
    const int m0 = blockIdx.y * 128, n0 = blockIdx.x * 128;
    const int xr = tid & 127, xk = (tid >> 7) * 8;
    const int wr = tid >> 4,  wc = (tid & 15) * 8;

    ull acc[8][4];
    #pragma unroll
    for (int i = 0; i < 8; i++)
        #pragma unroll
        for (int j = 0; j < 4; j++) acc[i][j] = 0ull;

    float4 xa = *(const float4*)&X[(size_t)(m0 + xr) * Dm + xk];
    float4 xb = *(const float4*)&X[(size_t)(m0 + xr) * Dm + xk + 4];
    float4 wa = *(const float4*)&W[(size_t)wr * Dm + n0 + wc];
    float4 wb = *(const float4*)&W[(size_t)wr * Dm + n0 + wc + 4];

    for (int t = 0; t < 64; t++) {
        Xs[xk + 0][xr] = xa.x; Xs[xk + 1][xr] = xa.y;
        Xs[xk + 2][xr] = xa.z; Xs[xk + 3][xr] = xa.w;
        Xs[xk + 4][xr] = xb.x; Xs[xk + 5][xr] = xb.y;
        Xs[xk + 6][xr] = xb.z; Xs[xk + 7][xr] = xb.w;
        *(float4*)&Ws[wr][wc] = wa;
        *(float4*)&Ws[wr][wc + 4] = wb;
        __syncthreads();
        if (t < 63) {
            const int k0 = (t + 1) * 16;
            xa = *(const float4*)&X[(size_t)(m0 + xr) * Dm + k0 + xk];
            xb = *(const float4*)&X[(size_t)(m0 + xr) * Dm + k0 + xk + 4];
            wa = *(const float4*)&W[(size_t)(k0 + wr) * Dm + n0 + wc];
            wb = *(const float4*)&W[(size_t)(k0 + wr) * Dm + n0 + wc + 4];
        }
        #pragma unroll
        for (int kk = 0; kk < 16; kk++) {
            float4 a0 = *(const float4*)&Xs[kk][ty * 8];
            float4 a1 = *(const float4*)&Xs[kk][ty * 8 + 4];
            ulonglong2 b0 = *(const ulonglong2*)&Ws[kk][tx * 4];
            ulonglong2 b1 = *(const ulonglong2*)&Ws[kk][64 + tx * 4];
            ull p;
            p = pack2(a0.x, a0.x); fma2(acc[0][0], p, b0.x); fma2(acc[0][1], p, b0.y); fma2(acc[0][2], p, b1.x); fma2(acc[0][3], p, b1.y);
            p = pack2(a0.y, a0.y); fma2(acc[1][0], p, b0.x); fma2(acc[1][1], p, b0.y); fma2(acc[1][2], p, b1.x); fma2(acc[1][3], p, b1.y);
            p = pack2(a0.z, a0.z); fma2(acc[2][0], p, b0.x); fma2(acc[2][1], p, b0.y); fma2(acc[2][2], p, b1.x); fma2(acc[2][3], p, b1.y);
            p = pack2(a0.w, a0.w); fma2(acc[3][0], p, b0.x); fma2(acc[3][1], p, b0.y); fma2(acc[3][2], p, b1.x); fma2(acc[3][3], p, b1.y);
            p = pack2(a1.x, a1.x); fma2(acc[4][0], p, b0.x); fma2(acc[4][1], p, b0.y); fma2(acc[4][2], p, b1.x); fma2(acc[4][3], p, b1.y);
            p = pack2(a1.y, a1.y); fma2(acc[5][0], p, b0.x); fma2(acc[5][1], p, b0.y); fma2(acc[5][2], p, b1.x); fma2(acc[5][3], p, b1.y);
            p = pack2(a1.z, a1.z); fma2(acc[6][0], p, b0.x); fma2(acc[6][1], p, b0.y); fma2(acc[6][2], p, b1.x); fma2(acc[6][3], p, b1.y);
            p = pack2(a1.w, a1.w); fma2(acc[7][0], p, b0.x); fma2(acc[7][1], p, b0.y); fma2(acc[7][2], p, b1.x); fma2(acc[7][3], p, b1.y);
        }
        __syncthreads();
    }

    float4 bl = *(const float4*)&bias[n0 + tx * 4];
    float4 bh = *(const float4*)&bias[n0 + 64 + tx * 4];
    const int h0 = n0 >> 6;
    #pragma unroll
    for (int i = 0; i < 8; i++) {
        const int m = m0 + ty * 8 + i, bb = m >> 11, s = m & 2047;
        float2 c0 = unpack2(acc[i][0]), c1 = unpack2(acc[i][1]);
        float4 v = make_float4(c0.x + bl.x, c0.y + bl.y, c1.x + bl.z, c1.y + bl.w);
        *(float4*)&outp[((size_t)((bb * Hn + h0) * Sq + s)) * DH + tx * 4] = v;
        c0 = unpack2(acc[i][2]); c1 = unpack2(acc[i][3]);
        v = make_float4(c0.x + bh.x, c0.y + bh.y, c1.x + bh.z, c1.y + bh.w);
        *(float4*)&outp[((size_t)((bb * Hn + h0 + 1) * Sq + s)) * DH + tx * 4] = v;
    }
}

// ---------------------------------------------------------------------------
// Kernel 2: flash attention, Bq=128, Bk=64, 256 threads, 8x4 micro.
// Q and K staged as f32x2 pairs over d -> zero pack movs in scores loop.
// ---------------------------------------------------------------------------
#define QD 0        // Qd[32 dp][260]: pair (Q[r][2dp],Q[r][2dp+1]) at 2r
#define KD 8320     // Kd[32 dp][132]: pair over d at 2c
#define VS 12544    // Vs[2][64][68] natural [j][dc]
#define PS 21248    // Ps[64][128] P transposed, unit-swizzled
#define PB 29440    // pb[128][132]
#define SMF 46336
// relTp overlay at KD: [32 dp][288]: pair (rel[t][2dp],rel[t][2dp+1]) at 2t
// (extends into Vs region; dead before first Vs/Kd write)

extern __shared__ __align__(16) float sm[];

__global__ __launch_bounds__(256, 1)
void attn_kernel(const float* __restrict__ mask,
                 const float* __restrict__ rel,
                 float* __restrict__ out)
{
    float* Qd = sm + QD;
    float* Kd = sm + KD;
    float* Vs = sm + VS;
    float* Ps = sm + PS;
    float* pb = sm + PB;
    float* relTp = sm + KD;

    const int tid = threadIdx.x;
    const int tx = tid & 15, ty = tid >> 4;
    const int bh = blockIdx.y, b = bh >> 4, h = bh & 15;
    const int q0 = blockIdx.x * 128;

    const float* Qg = g_Q + (size_t)bh * (Sq * DH);
    const float* Kg = g_K + (size_t)bh * (Sq * DH);
    const float* Vg = g_V + (size_t)bh * (Sq * DH);
    const float* maskb = mask + (size_t)b * Sq;

    // ---- stage Q as d-pairs ----
    {
        const int qr = tid & 127, qc0 = (tid >> 7) * 32;
        #pragma unroll
        for (int u = 0; u < 8; u++) {
            int d = qc0 + 4 * u;
            float4 v = *(const float4*)&Qg[(size_t)(q0 + qr) * DH + d];
            *(float2*)&Qd[(d >> 1) * 260 + 2 * qr]       = make_float2(v.x, v.y);
            *(float2*)&Qd[((d >> 1) + 1) * 260 + 2 * qr] = make_float2(v.z, v.w);
        }
    }
    // ---- stage rel as d-pairs, zero-pad t in [129,144) ----
    for (int i = tid; i < 32 * 15; i += 256) {
        int dp = i / 15, t = 129 + (i % 15);
        *(float2*)&relTp[dp * 288 + 2 * t] = make_float2(0.f, 0.f);
    }
    for (int i = tid; i < NREL * 16; i += 256) {
        int t = i >> 4, d = (i & 15) * 4;
        float4 v = *(const float4*)&rel[t * DH + d];
        *(float2*)&relTp[(d >> 1) * 288 + 2 * t]       = make_float2(v.x, v.y);
        *(float2*)&relTp[((d >> 1) + 1) * 288 + 2 * t] = make_float2(v.z, v.w);
    }
    __syncthreads();

    // ---- pb[r][t] = q_r . rel_t, d-packed, two passes of 4 rows ----
    #pragma unroll
    for (int pass = 0; pass < 2; pass++) {
        const int rbase = ty * 8 + pass * 4;
        ull pa[4][9];
        #pragma unroll
        for (int i = 0; i < 4; i++)
            #pragma unroll
            for (int tt = 0; tt < 9; tt++) pa[i][tt] = 0ull;
        for (int dp = 0; dp < 32; dp++) {
            ulonglong2 q01 = *(const ulonglong2*)&Qd[dp * 260 + 2 * rbase];
            ulonglong2 q23 = *(const ulonglong2*)&Qd[dp * 260 + 2 * rbase + 4];
            #pragma unroll
            for (int tt = 0; tt < 9; tt++) {
                ull rv = *(const ull*)&relTp[dp * 288 + 2 * (tx + 16 * tt)];
                fma2(pa[0][tt], q01.x, rv);
                fma2(pa[1][tt], q01.y, rv);
                fma2(pa[2][tt], q23.x, rv);
                fma2(pa[3][tt], q23.y, rv);
            }
        }
        #pragma unroll
        for (int tt = 0; tt < 9; tt++) {
            int t = tx + 16 * tt;
            if (t < 132) {
                #pragma unroll
                for (int i = 0; i < 4; i++) {
                    float2 f = unpack2(pa[i][tt]);
                    pb[(rbase + i) * 132 + t] = f.x + f.y;
                }
            }
        }
    }
    __syncthreads();

    float pLo[8], pHi[8];
    #pragma unroll
    for (int i = 0; i < 8; i++) {
        pLo[i] = pb[(ty * 8 + i) * 132];
        pHi[i] = pb[(ty * 8 + i) * 132 + 128];
    }

    // ---- prologue: V0 via cp.async, K0 via LDG ----
    const int krow = tid & 63, kd0 = (tid >> 6) * 16;
    #pragma unroll
    for (int c = 0; c < 4; c++)
        cp16(&Vs[krow * 68 + kd0 + 4 * c], &Vg[(size_t)krow * DH + kd0 + 4 * c]);
    asm volatile("cp.async.commit_group;" ::: "memory");
    float4 kr4[4];
    #pragma unroll
    for (int c = 0; c < 4; c++)
        kr4[c] = *(const float4*)&Kg[(size_t)krow * DH + kd0 + 4 * c];

    ull o[8][2];
    float m_i[8], l_i[8];
    #pragma unroll
    for (int i = 0; i < 8; i++) {
        o[i][0] = 0ull; o[i][1] = 0ull; m_i[i] = -INFINITY; l_i[i] = 0.f;
    }

    for (int kt = 0; kt < 32; kt++) {
        const int buf = kt & 1;
        const int k0 = kt * 64;
        __syncthreads();

        // stage K as d-pairs
        #pragma unroll
        for (int c = 0; c < 4; c++) {
            int d = kd0 + 4 * c;
            *(float2*)&Kd[(d >> 1) * 132 + 2 * krow]       = make_float2(kr4[c].x, kr4[c].y);
            *(float2*)&Kd[((d >> 1) + 1) * 132 + 2 * krow] = make_float2(kr4[c].z, kr4[c].w);
        }
        if (kt < 31) {
            const float* Vn = Vg + (size_t)(k0 + 64) * DH;
            const float* Kn = Kg + (size_t)(k0 + 64) * DH;
            float* Vd = Vs + (buf ^ 1) * 4352;
            #pragma unroll
            for (int c = 0; c < 4; c++)
                cp16(&Vd[krow * 68 + kd0 + 4 * c], &Vn[(size_t)krow * DH + kd0 + 4 * c]);
            asm volatile("cp.async.commit_group;" ::: "memory");
            #pragma unroll
            for (int c = 0; c < 4; c++)
                kr4[c] = *(const float4*)&Kn[(size_t)krow * DH + kd0 + 4 * c];
            asm volatile("cp.async.wait_group 1;" ::: "memory");
        } else {
            asm volatile("cp.async.wait_group 0;" ::: "memory");
        }
        __syncthreads();

        // ---- scores: d-packed, zero pack movs ----
        ull acc[8][4];
        #pragma unroll
        for (int i = 0; i < 8; i++)
            #pragma unroll
            for (int j = 0; j < 4; j++) acc[i][j] = 0ull;

        #pragma unroll 4
        for (int dp = 0; dp < 32; dp++) {
            ulonglong2 qa = *(const ulonglong2*)&Qd[dp * 260 + 16 * ty];
            ulonglong2 qb = *(const ulonglong2*)&Qd[dp * 260 + 16 * ty + 4];
            ulonglong2 qc = *(const ulonglong2*)&Qd[dp * 260 + 16 * ty + 8];
            ulonglong2 qe = *(const ulonglong2*)&Qd[dp * 260 + 16 * ty + 12];
            ulonglong2 ka = *(const ulonglong2*)&Kd[dp * 132 + 8 * tx];
            ulonglong2 kb = *(const ulonglong2*)&Kd[dp * 132 + 8 * tx + 4];
            fma2(acc[0][0], qa.x, ka.x); fma2(acc[0][1], qa.x, ka.y); fma2(acc[0][2], qa.x, kb.x); fma2(acc[0][3], qa.x, kb.y);
            fma2(acc[1][0], qa.y, ka.x); fma2(acc[1][1], qa.y, ka.y); fma2(acc[1][2], qa.y, kb.x); fma2(acc[1][3], qa.y, kb.y);
            fma2(acc[2][0], qb.x, ka.x); fma2(acc[2][1], qb.x, ka.y); fma2(acc[2][2], qb.x, kb.x); fma2(acc[2][3], qb.x, kb.y);
            fma2(acc[3][0], qb.y, ka.x); fma2(acc[3][1], qb.y, ka.y); fma2(acc[3][2], qb.y, kb.x); fma2(acc[3][3], qb.y, kb.y);
            fma2(acc[4][0], qc.x, ka.x); fma2(acc[4][1], qc.x, ka.y); fma2(acc[4][2], qc.x, kb.x); fma2(acc[4][3], qc.x, kb.y);
            fma2(acc[5][0], qc.y, ka.x); fma2(acc[5][1], qc.y, ka.y); fma2(acc[5][2], qc.y, kb.x); fma2(acc[5][3], qc.y, kb.y);
            fma2(acc[6][0], qe.x, ka.x); fma2(acc[6][1], qe.x, ka.y); fma2(acc[6][2], qe.x, kb.x); fma2(acc[6][3], qe.x, kb.y);
            fma2(acc[7][0], qe.y, ka.x); fma2(acc[7][1], qe.y, ka.y); fma2(acc[7][2], qe.y, kb.x); fma2(acc[7][3], qe.y, kb.y);
        }

        // ---- softmax (score = lane0 + lane1) ----
        float4 mk4 = *(const float4*)&maskb[k0 + tx * 4];
        const float mkf[4] = {mk4.x, mk4.y, mk4.z, mk4.w};
        const int ddmin = k0 - (q0 + 127), ddmax = k0 + 63 - q0;
        const bool gen = (ddmax > -64) && (ddmin < 64);
        float pv[8][4];
        #pragma unroll
        for (int i = 0; i < 8; i++) {
            float s[4];
            #pragma unroll
            for (int jj = 0; jj < 4; jj++) {
                float2 f = unpack2(acc[i][jj]);
                s[jj] = f.x + f.y;
            }
            if (gen) {
                const int rg = q0 + ty * 8 + i;
                #pragma unroll
                for (int jj = 0; jj < 4; jj++) {
                    int dd = k0 + tx * 4 + jj - rg;
                    dd = dd < -64 ? -64 : (dd > 64 ? 64 : dd);
                    s[jj] = (s[jj] + pb[(ty * 8 + i) * 132 + dd + 64]) * 0.125f + mkf[jj];
                }
            } else {
                const float bi = (ddmin >= 64) ? pHi[i] : pLo[i];
                #pragma unroll
                for (int jj = 0; jj < 4; jj++)
                    s[jj] = (s[jj] + bi) * 0.125f + mkf[jj];
            }
            float mx = fmaxf(fmaxf(s[0], s[1]), fmaxf(s[2], s[3]));
            #pragma unroll
            for (int off = 8; off; off >>= 1)
                mx = fmaxf(mx, __shfl_xor_sync(0xffffffffu, mx, off, 16));
            const float mnew = fmaxf(m_i[i], mx);
            const float alpha = __expf(m_i[i] - mnew);
            float rs = 0.f;
            #pragma unroll
            for (int jj = 0; jj < 4; jj++) {
                float p = __expf(s[jj] - mnew);
                pv[i][jj] = p; rs += p;
            }
            #pragma unroll
            for (int off = 8; off; off >>= 1)
                rs += __shfl_xor_sync(0xffffffffu, rs, off, 16);
            l_i[i] = l_i[i] * alpha + rs;
            m_i[i] = mnew;
            ull a2 = pack2(alpha, alpha);
            o[i][0] = mul2(o[i][0], a2);
            o[i][1] = mul2(o[i][1], a2);
        }

        // ---- stage P transposed with unit swizzle ----
        {
            const int swz = tx & 7;
            #pragma unroll
            for (int jj = 0; jj < 4; jj++) {
                float* bp = Ps + (tx * 4 + jj) * 128;
                *(float4*)(bp + 4 * ((2 * ty) ^ swz)) =
                    make_float4(pv[0][jj], pv[1][jj], pv[2][jj], pv[3][jj]);
                *(float4*)(bp + 4 * ((2 * ty + 1) ^ swz)) =
                    make_float4(pv[4][jj], pv[5][jj], pv[6][jj], pv[7][jj]);
            }
        }
        __syncthreads();

        // ---- O += P V ----
        const float* Vb = Vs + buf * 4352;
        #pragma unroll 4
        for (int j = 0; j < 64; j++) {
            const int swz = (j >> 2) & 7;
            float4 a0 = *(const float4*)(Ps + j * 128 + 4 * ((2 * ty) ^ swz));
            float4 a1 = *(const float4*)(Ps + j * 128 + 4 * ((2 * ty + 1) ^ swz));
            ulonglong2 bv = *(const ulonglong2*)&Vb[j * 68 + tx * 4];
            ull p;
            p = pack2(a0.x, a0.x); fma2(o[0][0], p, bv.x); fma2(o[0][1], p, bv.y);
            p = pack2(a0.y, a0.y); fma2(o[1][0], p, bv.x); fma2(o[1][1], p, bv.y);
            p = pack2(a0.z, a0.z); fma2(o[2][0], p, bv.x); fma2(o[2][1], p, bv.y);
            p = pack2(a0.w, a0.w); fma2(o[3][0], p, bv.x); fma2(o[3][1], p, bv.y);
            p = pack2(a1.x, a1.x); fma2(o[4][0], p, bv.x); fma2(o[4][1], p, bv.y);
            p = pack2(a1.y, a1.y); fma2(o[5][0], p, bv.x); fma2(o[5][1], p, bv.y);
            p = pack2(a1.z, a1.z); fma2(o[6][0], p, bv.x); fma2(o[6][1], p, bv.y);
            p = pack2(a1.w, a1.w); fma2(o[7][0], p, bv.x); fma2(o[7][1], p, bv.y);
        }
    }

    #pragma unroll
    for (int i = 0; i < 8; i++) {
        const int qg = q0 + ty * 8 + i;
        const float inv = 1.f / l_i[i];
        float2 c0 = unpack2(o[i][0]), c1 = unpack2(o[i][1]);
        float4 v = make_float4(c0.x * inv, c0.y * inv, c1.x * inv, c1.y * inv);
        *(float4*)&out[((size_t)(b * Sq + qg)) * Dm + h * DH + tx * 4] = v;
    }
}

extern "C" void kernel_launch(void* const* d_in, const int* in_sizes, int n_in,
                              void* d_out, int out_size)
{
    const float* query = (const float*)d_in[0];
    const float* key   = (const float*)d_in[1];
    const float* value = (const float*)d_in[2];
    const float* mask  = (const float*)d_in[3];
    const float* Wq    = (const float*)d_in[4];
    const float* bq    = (const float*)d_in[5];
    const float* Wk    = (const float*)d_in[6];
    const float* bk    = (const float*)d_in[7];
    const float* Wv    = (const float*)d_in[8];
    const float* bv    = (const float*)d_in[9];
    const float* rel   = (const float*)d_in[10];
    float* out = (float*)d_out;
    (void)in_sizes; (void)n_in; (void)out_size;

    const int ATTN_SMEM = SMF * (int)sizeof(float);
    cudaFuncSetAttribute(attn_kernel,
                         cudaFuncAttributeMaxDynamicSharedMemorySize, ATTN_SMEM);

    dim3 gemm_grid(Dm / 128, (Bz * Sq) / 128, 3);
    qkv_proj_kernel<<<gemm_grid, 256>>>(query, key, value, Wq, Wk, Wv, bq, bk, bv);

    dim3 attn_grid(Sq / 128, Bz * Hn);
    attn_kernel<<<attn_grid, 256, ATTN_SMEM>>>(mask, rel, out);
}

// round 8
// speedup vs baseline: 1.5114x; 1.5114x over previous
#include <cuda_runtime.h>
#include <math.h>

#define Bz 2
#define Sq 2048
#define Dm 1024
#define Hn 16
#define DH 64
#define NREL 129
#define BHN (Bz*Hn)

typedef unsigned long long ull;

__device__ float g_Q[BHN * Sq * DH];
__device__ float g_K[BHN * Sq * DH];
__device__ float g_V[BHN * Sq * DH];

__device__ __forceinline__ ull pack2(float lo, float hi) {
    ull r; asm("mov.b64 %0, {%1, %2};" : "=l"(r) : "f"(lo), "f"(hi)); return r;
}
__device__ __forceinline__ float2 unpack2(ull v) {
    float2 r; asm("mov.b64 {%0, %1}, %2;" : "=f"(r.x), "=f"(r.y) : "l"(v)); return r;
}
__device__ __forceinline__ void fma2(ull& a, ull x, ull y) {
    asm("fma.rn.f32x2 %0, %1, %2, %0;" : "+l"(a) : "l"(x), "l"(y));
}
__device__ __forceinline__ unsigned tf32u(float f) {
    unsigned r; asm("cvt.rna.tf32.f32 %0, %1;" : "=r"(r) : "f"(f)); return r;
}
__device__ __forceinline__ float tf32f(float f) { return __uint_as_float(tf32u(f)); }
__device__ __forceinline__ void mma_tf32(float& c0, float& c1, float& c2, float& c3,
                                         unsigned a0, unsigned a1, unsigned a2, unsigned a3,
                                         unsigned b0, unsigned b1) {
    asm("mma.sync.aligned.m16n8k8.row.col.f32.tf32.tf32.f32 "
        "{%0,%1,%2,%3}, {%4,%5,%6,%7}, {%8,%9}, {%0,%1,%2,%3};"
        : "+f"(c0), "+f"(c1), "+f"(c2), "+f"(c3)
        : "r"(a0), "r"(a1), "r"(a2), "r"(a3), "r"(b0), "r"(b1));
}

// ---------------------------------------------------------------------------
// Kernel 1: QKV projection (round-5 FFMA2 version, unchanged — full fp32).
// ---------------------------------------------------------------------------
__device__ __forceinline__ ull mul2(ull x, ull y) {
    ull r; asm("mul.rn.f32x2 %0, %1, %2;" : "=l"(r) : "l"(x), "l"(y)); return r;
}

__global__ __launch_bounds__(256, 2)
void qkv_proj_kernel(const float* __restrict__ Xq, const float* __restrict__ Xk,
                     const float* __restrict__ Xv,
                     const float* __restrict__ Wq, const float* __restrict__ Wk,
                     const float* __restrict__ Wv,
                     const float* __restrict__ bq, const float* __restrict__ bk,
                     const float* __restrict__ bv)
{
    const float* X; const float* W; const float* bias; float* outp;
    if (blockIdx.z == 0)      { X = Xq; W = Wq; bias = bq; outp = g_Q; }
    else if (blockIdx.z == 1) { X = Xk; W = Wk; bias = bk; outp = g_K; }
    else                      { X = Xv; W = Wv; bias = bv; outp = g_V; }

    __shared__ __align__(16) float Xs[16][132];
    __shared__ __align__(16) float Ws[16][132];

    const int tid = threadIdx.x;
    const int tx = tid & 15, ty = tid >> 4;
    const int m0 = blockIdx.y * 128, n0 = blockIdx.x * 128;
    const int xr = tid & 127, xk = (tid >> 7) * 8;
    const int wr = tid >> 4,  wc = (tid & 15) * 8;

    ull acc[8][4];
    #pragma unroll
    for (int i = 0; i < 8; i++)
        #pragma unroll
        for (int j = 0; j < 4; j++) acc[i][j] = 0ull;

    float4 xa = *(const float4*)&X[(size_t)(m0 + xr) * Dm + xk];
    float4 xb = *(const float4*)&X[(size_t)(m0 + xr) * Dm + xk + 4];
    float4 wa = *(const float4*)&W[(size_t)wr * Dm + n0 + wc];
    float4 wb = *(const float4*)&W[(size_t)wr * Dm + n0 + wc + 4];

    for (int t = 0; t < 64; t++) {
        Xs[xk + 0][xr] = xa.x; Xs[xk + 1][xr] = xa.y;
        Xs[xk + 2][xr] = xa.z; Xs[xk + 3][xr] = xa.w;
        Xs[xk + 4][xr] = xb.x; Xs[xk + 5][xr] = xb.y;
        Xs[xk + 6][xr] = xb.z; Xs[xk + 7][xr] = xb.w;
        *(float4*)&Ws[wr][wc] = wa;
        *(float4*)&Ws[wr][wc + 4] = wb;
        __syncthreads();
        if (t < 63) {
            const int k0 = (t + 1) * 16;
            xa = *(const float4*)&X[(size_t)(m0 + xr) * Dm + k0 + xk];
            xb = *(const float4*)&X[(size_t)(m0 + xr) * Dm + k0 + xk + 4];
            wa = *(const float4*)&W[(size_t)(k0 + wr) * Dm + n0 + wc];
            wb = *(const float4*)&W[(size_t)(k0 + wr) * Dm + n0 + wc + 4];
        }
        #pragma unroll
        for (int kk = 0; kk < 16; kk++) {
            float4 a0 = *(const float4*)&Xs[kk][ty * 8];
            float4 a1 = *(const float4*)&Xs[kk][ty * 8 + 4];
            ulonglong2 b0 = *(const ulonglong2*)&Ws[kk][tx * 4];
            ulonglong2 b1 = *(const ulonglong2*)&Ws[kk][64 + tx * 4];
            ull p;
            p = pack2(a0.x, a0.x); fma2(acc[0][0], p, b0.x); fma2(acc[0][1], p, b0.y); fma2(acc[0][2], p, b1.x); fma2(acc[0][3], p, b1.y);
            p = pack2(a0.y, a0.y); fma2(acc[1][0], p, b0.x); fma2(acc[1][1], p, b0.y); fma2(acc[1][2], p, b1.x); fma2(acc[1][3], p, b1.y);
            p = pack2(a0.z, a0.z); fma2(acc[2][0], p, b0.x); fma2(acc[2][1], p, b0.y); fma2(acc[2][2], p, b1.x); fma2(acc[2][3], p, b1.y);
            p = pack2(a0.w, a0.w); fma2(acc[3][0], p, b0.x); fma2(acc[3][1], p, b0.y); fma2(acc[3][2], p, b1.x); fma2(acc[3][3], p, b1.y);
            p = pack2(a1.x, a1.x); fma2(acc[4][0], p, b0.x); fma2(acc[4][1], p, b0.y); fma2(acc[4][2], p, b1.x); fma2(acc[4][3], p, b1.y);
            p = pack2(a1.y, a1.y); fma2(acc[5][0], p, b0.x); fma2(acc[5][1], p, b0.y); fma2(acc[5][2], p, b1.x); fma2(acc[5][3], p, b1.y);
            p = pack2(a1.z, a1.z); fma2(acc[6][0], p, b0.x); fma2(acc[6][1], p, b0.y); fma2(acc[6][2], p, b1.x); fma2(acc[6][3], p, b1.y);
            p = pack2(a1.w, a1.w); fma2(acc[7][0], p, b0.x); fma2(acc[7][1], p, b0.y); fma2(acc[7][2], p, b1.x); fma2(acc[7][3], p, b1.y);
        }
        __syncthreads();
    }

    float4 bl = *(const float4*)&bias[n0 + tx * 4];
    float4 bh = *(const float4*)&bias[n0 + 64 + tx * 4];
    const int h0 = n0 >> 6;
    #pragma unroll
    for (int i = 0; i < 8; i++) {
        const int m = m0 + ty * 8 + i, bb = m >> 11, s = m & 2047;
        float2 c0 = unpack2(acc[i][0]), c1 = unpack2(acc[i][1]);
        float4 v = make_float4(c0.x + bl.x, c0.y + bl.y, c1.x + bl.z, c1.y + bl.w);
        *(float4*)&outp[((size_t)((bb * Hn + h0) * Sq + s)) * DH + tx * 4] = v;
        c0 = unpack2(acc[i][2]); c1 = unpack2(acc[i][3]);
        v = make_float4(c0.x + bh.x, c0.y + bh.y, c1.x + bh.z, c1.y + bh.w);
        *(float4*)&outp[((size_t)((bb * Hn + h0 + 1) * Sq + s)) * DH + tx * 4] = v;
    }
}

// ---------------------------------------------------------------------------
// Kernel 2: flash attention on tf32 mma.sync (m16n8k8).
// Bq=128 (8 warps x 16 rows), Bk=64, 256 threads.
// ---------------------------------------------------------------------------
#define QS_O 0        // Qs[128][68] natural, tf32
#define KS_O 8704     // Ks[2][64][68] natural, tf32
#define VT_O 17408    // Vt[2][64][68] transposed [dc][j], tf32
#define PS_O 26112    // Ps[128][68] natural, tf32  (relS overlay: [129][66])
#define PB_O 34816    // pb[128][132] fp32
#define MK_O 51712    // maskS[68]
#define SMF  51780

extern __shared__ __align__(16) float sm[];

__global__ __launch_bounds__(256, 1)
void attn_kernel(const float* __restrict__ mask,
                 const float* __restrict__ rel,
                 float* __restrict__ out)
{
    float* Qs = sm + QS_O;
    float* Ks = sm + KS_O;
    float* Vt = sm + VT_O;
    float* Ps = sm + PS_O;
    float* pb = sm + PB_O;
    float* maskS = sm + MK_O;
    float* relS = sm + PS_O;   // stride 66, dead after pb phase

    const int tid = threadIdx.x;
    const int w = tid >> 5, lane = tid & 31;
    const int grp = lane >> 2, tig = lane & 3;
    const int bh = blockIdx.y, b = bh >> 4, h = bh & 15;
    const int q0 = blockIdx.x * 128;

    const float* Qg = g_Q + (size_t)bh * (Sq * DH);
    const float* Kg = g_K + (size_t)bh * (Sq * DH);
    const float* Vg = g_V + (size_t)bh * (Sq * DH);
    const float* maskb = mask + (size_t)b * Sq;

    // ---- stage Q (tf32) ----
    {
        const int qr = tid & 127, qc = (tid >> 7) * 32;
        #pragma unroll
        for (int u = 0; u < 8; u++) {
            float4 v = *(const float4*)&Qg[(size_t)(q0 + qr) * DH + qc + 4 * u];
            float4 t = make_float4(tf32f(v.x), tf32f(v.y), tf32f(v.z), tf32f(v.w));
            *(float4*)&Qs[qr * 68 + qc + 4 * u] = t;
        }
    }
    // ---- stage rel (fp32, stride 66) ----
    for (int i = tid; i < NREL * 32; i += 256) {
        int t = i >> 5, dp = i & 31;
        *(float2*)&relS[t * 66 + 2 * dp] = *(const float2*)&rel[t * DH + 2 * dp];
    }
    // ---- prefetch tile 0 K/V/mask ----
    const int krow = tid & 63, kd0 = (tid >> 6) * 16;
    float4 kr4[4], vr4[4], mv;
    #pragma unroll
    for (int c = 0; c < 4; c++) {
        kr4[c] = *(const float4*)&Kg[(size_t)krow * DH + kd0 + 4 * c];
        vr4[c] = *(const float4*)&Vg[(size_t)krow * DH + kd0 + 4 * c];
    }
    if (tid < 16) mv = *(const float4*)&maskb[tid * 4];
    __syncthreads();

    // ---- pb[r][t] = q_r . rel_t  (FFMA2, d-packed) ----
    {
        const int tx = tid & 15, ty = tid >> 4;
        #pragma unroll
        for (int pass = 0; pass < 2; pass++) {
            const int rbase = ty * 8 + pass * 4;
            ull pa[4][9];
            #pragma unroll
            for (int i = 0; i < 4; i++)
                #pragma unroll
                for (int tt = 0; tt < 9; tt++) pa[i][tt] = 0ull;
            for (int dp = 0; dp < 32; dp++) {
                ull qv[4];
                #pragma unroll
                for (int i = 0; i < 4; i++)
                    qv[i] = *(const ull*)&Qs[(rbase + i) * 68 + 2 * dp];
                #pragma unroll
                for (int tt = 0; tt < 9; tt++) {
                    int t = tx + 16 * tt;
                    if (t < NREL) {
                        ull rv = *(const ull*)&relS[t * 66 + 2 * dp];
                        fma2(pa[0][tt], qv[0], rv);
                        fma2(pa[1][tt], qv[1], rv);
                        fma2(pa[2][tt], qv[2], rv);
                        fma2(pa[3][tt], qv[3], rv);
                    }
                }
            }
            #pragma unroll
            for (int tt = 0; tt < 9; tt++) {
                int t = tx + 16 * tt;
                if (t < NREL) {
                    #pragma unroll
                    for (int i = 0; i < 4; i++) {
                        float2 f = unpack2(pa[i][tt]);
                        pb[(rbase + i) * 132 + t] = f.x + f.y;
                    }
                }
            }
        }
    }
    __syncthreads();

    const int rlo = w * 16 + grp, rhi = rlo + 8;     // local q-rows
    const int rglo = q0 + rlo, rghi = q0 + rhi;      // global q-rows
    const float pLo_l = pb[rlo * 132],     pHi_l = pb[rlo * 132 + 128];
    const float pLo_h = pb[rhi * 132],     pHi_h = pb[rhi * 132 + 128];

    float o[8][4];
    #pragma unroll
    for (int n = 0; n < 8; n++)
        #pragma unroll
        for (int c = 0; c < 4; c++) o[n][c] = 0.f;
    float m_lo = -INFINITY, m_hi = -INFINITY, l_lo = 0.f, l_hi = 0.f;

    for (int kt = 0; kt < 32; kt++) {
        const int buf = kt & 1;
        const int k0 = kt * 64;
        float* Kb = Ks + buf * 4352;
        float* Vb = Vt + buf * 4352;

        // ---- stage this tile (cvt to tf32) ----
        #pragma unroll
        for (int c = 0; c < 4; c++) {
            float4 t = make_float4(tf32f(kr4[c].x), tf32f(kr4[c].y),
                                   tf32f(kr4[c].z), tf32f(kr4[c].w));
            *(float4*)&Kb[krow * 68 + kd0 + 4 * c] = t;
            Vb[(kd0 + 4 * c + 0) * 68 + krow] = tf32f(vr4[c].x);
            Vb[(kd0 + 4 * c + 1) * 68 + krow] = tf32f(vr4[c].y);
            Vb[(kd0 + 4 * c + 2) * 68 + krow] = tf32f(vr4[c].z);
            Vb[(kd0 + 4 * c + 3) * 68 + krow] = tf32f(vr4[c].w);
        }
        if (tid < 16) *(float4*)&maskS[tid * 4] = mv;
        // ---- prefetch next tile ----
        if (kt < 31) {
            const float* Kn = Kg + (size_t)(k0 + 64) * DH;
            const float* Vn = Vg + (size_t)(k0 + 64) * DH;
            #pragma unroll
            for (int c = 0; c < 4; c++) {
                kr4[c] = *(const float4*)&Kn[(size_t)krow * DH + kd0 + 4 * c];
                vr4[c] = *(const float4*)&Vn[(size_t)krow * DH + kd0 + 4 * c];
            }
            if (tid < 16) mv = *(const float4*)&maskb[k0 + 64 + tid * 4];
        }
        __syncthreads();

        // ---- scores: S = Q K^T via tf32 mma ----
        float sc[8][4];
        #pragma unroll
        for (int n = 0; n < 8; n++)
            #pragma unroll
            for (int c = 0; c < 4; c++) sc[n][c] = 0.f;
        #pragma unroll
        for (int kk = 0; kk < 8; kk++) {
            unsigned a0 = __float_as_uint(Qs[rlo * 68 + kk * 8 + tig]);
            unsigned a1 = __float_as_uint(Qs[rhi * 68 + kk * 8 + tig]);
            unsigned a2 = __float_as_uint(Qs[rlo * 68 + kk * 8 + tig + 4]);
            unsigned a3 = __float_as_uint(Qs[rhi * 68 + kk * 8 + tig + 4]);
            #pragma unroll
            for (int n = 0; n < 8; n++) {
                unsigned b0 = __float_as_uint(Kb[(n * 8 + grp) * 68 + kk * 8 + tig]);
                unsigned b1 = __float_as_uint(Kb[(n * 8 + grp) * 68 + kk * 8 + tig + 4]);
                mma_tf32(sc[n][0], sc[n][1], sc[n][2], sc[n][3], a0, a1, a2, a3, b0, b1);
            }
        }

        // ---- softmax ----
        const int ddmin = k0 - (q0 + 127), ddmax = k0 + 63 - q0;
        const bool gen = (ddmax > -64) && (ddmin < 64);
        const float bC_l = (ddmin >= 64) ? pHi_l : pLo_l;
        const float bC_h = (ddmin >= 64) ? pHi_h : pLo_h;
        float mx_lo = -INFINITY, mx_hi = -INFINITY;
        #pragma unroll
        for (int n = 0; n < 8; n++) {
            const int c0 = n * 8 + 2 * tig;
            float2 mk = *(const float2*)&maskS[c0];
            float b00, b01, b10, b11;
            if (gen) {
                int d0 = k0 + c0 - rglo;
                int t00 = d0     < -64 ? 0 : (d0     > 64 ? 128 : d0 + 64);
                int t01 = d0 + 1 < -64 ? 0 : (d0 + 1 > 64 ? 128 : d0 + 65);
                int d1 = k0 + c0 - rghi;
                int t10 = d1     < -64 ? 0 : (d1     > 64 ? 128 : d1 + 64);
                int t11 = d1 + 1 < -64 ? 0 : (d1 + 1 > 64 ? 128 : d1 + 65);
                b00 = pb[rlo * 132 + t00]; b01 = pb[rlo * 132 + t01];
                b10 = pb[rhi * 132 + t10]; b11 = pb[rhi * 132 + t11];
            } else { b00 = b01 = bC_l; b10 = b11 = bC_h; }
            sc[n][0] = (sc[n][0] + b00) * 0.125f + mk.x;
            sc[n][1] = (sc[n][1] + b01) * 0.125f + mk.y;
            sc[n][2] = (sc[n][2] + b10) * 0.125f + mk.x;
            sc[n][3] = (sc[n][3] + b11) * 0.125f + mk.y;
            mx_lo = fmaxf(mx_lo, fmaxf(sc[n][0], sc[n][1]));
            mx_hi = fmaxf(mx_hi, fmaxf(sc[n][2], sc[n][3]));
        }
        mx_lo = fmaxf(mx_lo, __shfl_xor_sync(0xffffffffu, mx_lo, 1, 4));
        mx_lo = fmaxf(mx_lo, __shfl_xor_sync(0xffffffffu, mx_lo, 2, 4));
        mx_hi = fmaxf(mx_hi, __shfl_xor_sync(0xffffffffu, mx_hi, 1, 4));
        mx_hi = fmaxf(mx_hi, __shfl_xor_sync(0xffffffffu, mx_hi, 2, 4));
        const float mn_lo = fmaxf(m_lo, mx_lo), mn_hi = fmaxf(m_hi, mx_hi);
        const float al_lo = __expf(m_lo - mn_lo), al_hi = __expf(m_hi - mn_hi);
        float rs_lo = 0.f, rs_hi = 0.f;
        #pragma unroll
        for (int n = 0; n < 8; n++) {
            sc[n][0] = __expf(sc[n][0] - mn_lo); rs_lo += sc[n][0];
            sc[n][1] = __expf(sc[n][1] - mn_lo); rs_lo += sc[n][1];
            sc[n][2] = __expf(sc[n][2] - mn_hi); rs_hi += sc[n][2];
            sc[n][3] = __expf(sc[n][3] - mn_hi); rs_hi += sc[n][3];
        }
        rs_lo += __shfl_xor_sync(0xffffffffu, rs_lo, 1, 4);
        rs_lo += __shfl_xor_sync(0xffffffffu, rs_lo, 2, 4);
        rs_hi += __shfl_xor_sync(0xffffffffu, rs_hi, 1, 4);
        rs_hi += __shfl_xor_sync(0xffffffffu, rs_hi, 2, 4);
        l_lo = l_lo * al_lo + rs_lo; m_lo = mn_lo;
        l_hi = l_hi * al_hi + rs_hi; m_hi = mn_hi;
        #pragma unroll
        for (int n = 0; n < 8; n++) {
            o[n][0] *= al_lo; o[n][1] *= al_lo;
            o[n][2] *= al_hi; o[n][3] *= al_hi;
        }
        // ---- stage P (tf32) ----
        #pragma unroll
        for (int n = 0; n < 8; n++) {
            *(float2*)&Ps[rlo * 68 + n * 8 + 2 * tig] =
                make_float2(tf32f(sc[n][0]), tf32f(sc[n][1]));
            *(float2*)&Ps[rhi * 68 + n * 8 + 2 * tig] =
                make_float2(tf32f(sc[n][2]), tf32f(sc[n][3]));
        }
        __syncthreads();

        // ---- O += P V via tf32 mma ----
        #pragma unroll
        for (int jj = 0; jj < 8; jj++) {
            unsigned a0 = __float_as_uint(Ps[rlo * 68 + jj * 8 + tig]);
            unsigned a1 = __float_as_uint(Ps[rhi * 68 + jj * 8 + tig]);
            unsigned a2 = __float_as_uint(Ps[rlo * 68 + jj * 8 + tig + 4]);
            unsigned a3 = __float_as_uint(Ps[rhi * 68 + jj * 8 + tig + 4]);
            #pragma unroll
            for (int n = 0; n < 8; n++) {
                unsigned b0 = __float_as_uint(Vb[(n * 8 + grp) * 68 + jj * 8 + tig]);
                unsigned b1 = __float_as_uint(Vb[(n * 8 + grp) * 68 + jj * 8 + tig + 4]);
                mma_tf32(o[n][0], o[n][1], o[n][2], o[n][3], a0, a1, a2, a3, b0, b1);
            }
        }
    }

    // ---- epilogue ----
    const float inv_lo = 1.f / l_lo, inv_hi = 1.f / l_hi;
    #pragma unroll
    for (int n = 0; n < 8; n++) {
        const int col = h * DH + n * 8 + 2 * tig;
        *(float2*)&out[((size_t)(b * Sq + rglo)) * Dm + col] =
            make_float2(o[n][0] * inv_lo, o[n][1] * inv_lo);
        *(float2*)&out[((size_t)(b * Sq + rghi)) * Dm + col] =
            make_float2(o[n][2] * inv_hi, o[n][3] * inv_hi);
    }
}

extern "C" void kernel_launch(void* const* d_in, const int* in_sizes, int n_in,
                              void* d_out, int out_size)
{
    const float* query = (const float*)d_in[0];
    const float* key   = (const float*)d_in[1];
    const float* value = (const float*)d_in[2];
    const float* mask  = (const float*)d_in[3];
    const float* Wq    = (const float*)d_in[4];
    const float* bq    = (const float*)d_in[5];
    const float* Wk    = (const float*)d_in[6];
    const float* bk    = (const float*)d_in[7];
    const float* Wv    = (const float*)d_in[8];
    const float* bv    = (const float*)d_in[9];
    const float* rel   = (const float*)d_in[10];
    float* out = (float*)d_out;
    (void)in_sizes; (void)n_in; (void)out_size;

    const int ATTN_SMEM = SMF * (int)sizeof(float);
    cudaFuncSetAttribute(attn_kernel,
                         cudaFuncAttributeMaxDynamicSharedMemorySize, ATTN_SMEM);

    dim3 gemm_grid(Dm / 128, (Bz * Sq) / 128, 3);
    qkv_proj_kernel<<<gemm_grid, 256>>>(query, key, value, Wq, Wk, Wv, bq, bk, bv);

    dim3 attn_grid(Sq / 128, Bz * Hn);
    attn_kernel<<<attn_grid, 256, ATTN_SMEM>>>(mask, rel, out);
}